// round 12
// baseline (speedup 1.0000x reference)
#include <cuda_runtime.h>

// FastLearnableEMA — single-pass fused kernel (round 10: grid-balance fix).
//   a    = clip(sigmoid(logit_alpha), 1e-4, 1-1e-4)             [C]
//   u[t] = x[t]*w[t],  w[0]=1, w[t>0]=(1-a)*a^t
//   y[t] = cumsum_t(u) * min(a^-t, 1e8)     (== cumsum / max(a^t, 1e-8))
//
// Block = (batch b, 16-channel tile, full T), grid = 32*32 = 1024 CTAs
// (twice round-9's 512 -> wave-refill smooths the 4-vs-3 CTA/SM imbalance).
// Each warp owns TWO 16-t chunks: lanes 0-15 = chunk 2w, lanes 16-31 =
// chunk 2w+1 (one channel per lane within each half). A tile is 16 chunks
// x 16 t = 256 t; 8 tiles cover T. Cross-chunk prefix via double-buffered
// smem, one barrier per tile. x read once (streaming), y written once
// (streaming): 256 MB HBM traffic.

#define T_LEN   2048
#define C_LEN   512
#define CT      16                 // channels per block
#define NCHUNK  16                 // chunks per tile (8 warps x 2)
#define LT      16                 // t per chunk
#define TILE_T  (NCHUNK * LT)      // 256
#define NTILES  (T_LEN / TILE_T)   // 8
#define CLAMP_LO 1e-4f
#define CLAMP_HI (1.0f - 1e-4f)
#define INV_EPS  1e8f              // 1/eps

__global__ void __launch_bounds__(256, 4) ema_fused(
    const float* __restrict__ x,
    const float* __restrict__ logit_alpha,
    float* __restrict__ y)
{
    const int warp = threadIdx.x >> 5;
    const int lane = threadIdx.x & 31;
    const int q    = lane >> 4;                       // which chunk-half of warp
    const int cl   = lane & 15;                       // channel within tile
    const int k    = (warp << 1) | q;                 // chunk id 0..15

    const int b    = blockIdx.x >> 5;                 // C/CT = 32 ctiles per b
    const int c    = ((blockIdx.x & 31) * CT) + cl;

    __shared__ float sm_part[2][NCHUNK][CT];
    __shared__ float sm_base[2][CT];

    // per-channel constants
    float la  = logit_alpha[c];
    float a   = 1.0f / (1.0f + expf(-la));
    a = fminf(fmaxf(a, CLAMP_LO), CLAMP_HI);
    const float oma   = 1.0f - a;
    const float inv_a = 1.0f / a;
    const float lg2a  = log2f(a);

    // a^TILE_T and a^-TILE_T (tile stride = 256 = 2^8) by repeated squaring
    float aT = a;
    #pragma unroll
    for (int i = 0; i < 8; i++) aT *= aT;             // a^256 (underflow->0 ok)
    float iaT = inv_a;
    #pragma unroll
    for (int i = 0; i < 8; i++) iaT *= iaT;           // a^-256 (overflow->inf, clamped)

    // chunk-start powers at t = k*LT (exact 1.0 for chunk 0)
    const float t0k   = (float)(k * LT);
    float ap     = (k == 0) ? 1.0f : exp2f(t0k * lg2a);
    float inv_ap = (k == 0) ? 1.0f : exp2f(-t0k * lg2a);

    if (threadIdx.x < CT) sm_base[0][threadIdx.x] = 0.0f;
    // ordered by the first tile's __syncthreads()

    const size_t row = (size_t)b * T_LEN * C_LEN + c;

    #pragma unroll 1
    for (int tile = 0; tile < NTILES; tile++) {
        const int p     = tile & 1;
        const int tbase = tile * TILE_T + k * LT;
        const float* xp = x + row + (size_t)tbase * C_LEN;
        float*       yp = y + row + (size_t)tbase * C_LEN;

        // ---- load this chunk's 16 t (streaming; 2 x 64B rows per warp instr)
        float v[LT];
        #pragma unroll
        for (int i = 0; i < LT; i++)
            v[i] = __ldcs(xp + (size_t)i * C_LEN);

        // ---- chunk sum of u
        const bool has_t0 = (tile == 0) && (k == 0);
        float ap_i = ap;
        float S = 0.0f;
        #pragma unroll
        for (int i = 0; i < LT; i++) {
            float wm = (has_t0 && i == 0) ? 1.0f : oma;
            S = fmaf(v[i] * wm, ap_i, S);
            ap_i *= a;
        }
        sm_part[p][k][cl] = S;
        __syncthreads();   // orders sm_part[p] writes + prev tile's sm_base[p]

        // ---- exclusive prefix over the 16 chunks + running base
        float base = sm_base[p][cl];
        #pragma unroll
        for (int j = 0; j < NCHUNK - 1; j++)
            if (j < k) base += sm_part[p][j][cl];     // broadcast reads
        if (k == NCHUNK - 1)
            sm_base[p ^ 1][cl] = base + S;            // next tile's running total

        // ---- local scan; reuse v[] for y
        float Sc    = base;
        float ap_j  = ap;
        float iap_j = inv_ap;
        #pragma unroll
        for (int i = 0; i < LT; i++) {
            float wm = (has_t0 && i == 0) ? 1.0f : oma;
            Sc = fmaf(v[i] * wm, ap_j, Sc);
            v[i] = Sc * fminf(iap_j, INV_EPS);        // = Sc / max(a^t, eps)
            ap_j  *= a;
            iap_j *= inv_a;
        }
        #pragma unroll
        for (int i = 0; i < LT; i++)
            __stcs(yp + (size_t)i * C_LEN, v[i]);

        // advance chunk-start powers by one tile (256 t)
        ap     *= aT;
        inv_ap *= iaT;
    }
}

extern "C" void kernel_launch(void* const* d_in, const int* in_sizes, int n_in,
                              void* d_out, int out_size)
{
    const float* x  = (const float*)d_in[0];
    const float* la = (const float*)d_in[1];
    float*       y  = (float*)d_out;

    int B = in_sizes[0] / (T_LEN * C_LEN);        // 32
    int blocks = B * (C_LEN / CT);                // 1024
    ema_fused<<<blocks, 256>>>(x, la, y);
}